// round 15
// baseline (speedup 1.0000x reference)
#include <cuda_runtime.h>
#include <cuda_bf16.h>
#include <math.h>

#define BB 8
#define NQ 900
#define DD 256
#define HH 8
#define HD 32
#define PP 4
#define BEV 200
#define FFN_D 512
#define M_ROWS (BB*NQ)   // 7200

// ---------------- consolidated scratch arena (no allocation) ----------------
// f32 regions
#define OFF_QKV   0
#define OFF_Q1    (OFF_QKV + M_ROWS*768)
#define OFF_Q2    (OFF_Q1  + M_ROWS*DD)
#define OFF_QU2   (OFF_Q2  + M_ROWS*DD)
#define OFF_OFFS  (OFF_QU2 + M_ROWS*DD)
#define OFF_WT    (OFF_OFFS + M_ROWS*64)
// u32 split regions (each slot 4B; offsets in 4B units)
#define OFF_QINH  (OFF_WT   + M_ROWS*32)
#define OFF_QINL  (OFF_QINH + M_ROWS*128)
#define OFF_ATTH  (OFF_QINL + M_ROWS*128)
#define OFF_ATTL  (OFF_ATTH + M_ROWS*128)
#define OFF_FUSH  (OFF_ATTL + M_ROWS*128)
#define OFF_FUSL  (OFF_FUSH + M_ROWS*128)
#define OFF_Q3H   (OFF_FUSL + M_ROWS*128)
#define OFF_Q3L   (OFF_Q3H  + M_ROWS*128)
#define OFF_H1H   (OFF_Q3L  + M_ROWS*128)
#define OFF_H1L   (OFF_H1H  + M_ROWS*256)
#define OFF_WIH   (OFF_H1L  + M_ROWS*256)
#define OFF_WIL   (OFF_WIH  + 768*128)
#define OFF_WOH   (OFF_WIL  + 768*128)
#define OFF_WOL   (OFF_WOH  + 256*128)
#define OFF_WCH   (OFF_WOL  + 256*128)
#define OFF_WCL   (OFF_WCH  + 256*128)
#define OFF_W1H   (OFF_WCL  + 256*128)
#define OFF_W1L   (OFF_W1H  + 512*128)
#define OFF_W2H   (OFF_W1L  + 512*128)
#define OFF_W2L   (OFF_W2H  + 256*256)
#define SCRATCH_TOTAL (OFF_W2L + 256*256)

__device__ float g_scratch[SCRATCH_TOTAL];

// ---------------- bf16 two-term split helper ----------------
__device__ __forceinline__ void cvt_pair(float x0, float x1, unsigned &hi, unsigned &lo)
{
    __nv_bfloat16 h0 = __float2bfloat16(x0);
    __nv_bfloat16 h1 = __float2bfloat16(x1);
    float l0 = x0 - __bfloat162float(h0);
    float l1 = x1 - __bfloat162float(h1);
    __nv_bfloat162 hp; hp.x = h0; hp.y = h1;
    __nv_bfloat162 lp = __floats2bfloat162_rn(l0, l1);
    hi = *reinterpret_cast<unsigned*>(&hp);
    lo = *reinterpret_cast<unsigned*>(&lp);
}

// split f32 array (npairs float2s) into bf16x2 hi/lo
__global__ void split_kernel(const float* __restrict__ src, unsigned* __restrict__ hi,
                             unsigned* __restrict__ lo, int npairs)
{
    int i = blockIdx.x * 256 + threadIdx.x;
    if (i >= npairs) return;
    float2 v = ((const float2*)src)[i];
    unsigned h, l;
    cvt_pair(v.x, v.y, h, l);
    hi[i] = h; lo[i] = l;
}

// ---------------- LayerNorm: f32 out ----------------
__global__ void ln_kernel(const float* __restrict__ x, const float* __restrict__ pos,
                          const float* __restrict__ gam, const float* __restrict__ bet,
                          float* __restrict__ out)
{
    __shared__ float sb[8];
    __shared__ float stat;
    int r = blockIdx.x, t = threadIdx.x;
    int lane = t & 31, w = t >> 5;
    float v = x[r*DD + t];
    if (pos) v += pos[r*DD + t];

    float s = v;
    #pragma unroll
    for (int o = 16; o; o >>= 1) s += __shfl_xor_sync(0xffffffffu, s, o);
    if (lane == 0) sb[w] = s;
    __syncthreads();
    if (t == 0) { float tot = 0.f; for (int i = 0; i < 8; i++) tot += sb[i]; stat = tot * (1.0f/DD); }
    __syncthreads();
    float mean = stat;
    float c = v - mean;
    __syncthreads();
    s = c * c;
    #pragma unroll
    for (int o = 16; o; o >>= 1) s += __shfl_xor_sync(0xffffffffu, s, o);
    if (lane == 0) sb[w] = s;
    __syncthreads();
    if (t == 0) { float tot = 0.f; for (int i = 0; i < 8; i++) tot += sb[i]; stat = rsqrtf(tot * (1.0f/DD) + 1e-5f); }
    __syncthreads();
    out[r*DD + t] = c * stat * gam[t] + bet[t];
}

// ---------------- LayerNorm: split bf16 hi/lo out ----------------
__global__ void ln_split_kernel(const float* __restrict__ x, const float* __restrict__ pos,
                                const float* __restrict__ gam, const float* __restrict__ bet,
                                unsigned* __restrict__ ohi, unsigned* __restrict__ olo)
{
    __shared__ float sb[8];
    __shared__ float stat;
    int r = blockIdx.x, t = threadIdx.x;
    int lane = t & 31, w = t >> 5;
    float v = x[r*DD + t];
    if (pos) v += pos[r*DD + t];

    float s = v;
    #pragma unroll
    for (int o = 16; o; o >>= 1) s += __shfl_xor_sync(0xffffffffu, s, o);
    if (lane == 0) sb[w] = s;
    __syncthreads();
    if (t == 0) { float tot = 0.f; for (int i = 0; i < 8; i++) tot += sb[i]; stat = tot * (1.0f/DD); }
    __syncthreads();
    float mean = stat;
    float c = v - mean;
    __syncthreads();
    s = c * c;
    #pragma unroll
    for (int o = 16; o; o >>= 1) s += __shfl_xor_sync(0xffffffffu, s, o);
    if (lane == 0) sb[w] = s;
    __syncthreads();
    if (t == 0) { float tot = 0.f; for (int i = 0; i < 8; i++) tot += sb[i]; stat = rsqrtf(tot * (1.0f/DD) + 1e-5f); }
    __syncthreads();
    float ov = c * stat * gam[t] + bet[t];
    float ov2 = __shfl_down_sync(0xffffffffu, ov, 1);
    if (!(t & 1)) {
        unsigned h, l;
        cvt_pair(ov, ov2, h, l);
        ohi[r*128 + (t >> 1)] = h;
        olo[r*128 + (t >> 1)] = l;
    }
}

// ---------------- Tensor-core GEMM on pre-split bf16 hi/lo operands ----------------
// C = A[M,K]*B[N,K]^T + bias. act: 0 = f32 out (+res), 2 = relu + split out (Chi/Clo).
// K2 = K/2 (u32 pairs). Tile 128x64, BK=16 (8 pairs), double-buffered.
#define MMA_BF16(c, a, b) \
    asm volatile("mma.sync.aligned.m16n8k16.row.col.f32.bf16.bf16.f32 " \
        "{%0,%1,%2,%3}, {%4,%5,%6,%7}, {%8,%9}, {%0,%1,%2,%3};" \
        : "+f"((c)[0]), "+f"((c)[1]), "+f"((c)[2]), "+f"((c)[3]) \
        : "r"((a)[0]), "r"((a)[1]), "r"((a)[2]), "r"((a)[3]), "r"((b)[0]), "r"((b)[1]))

__global__ __launch_bounds__(256, 2)
void gemm_tc2(const unsigned* __restrict__ Ahi, const unsigned* __restrict__ Alo,
              const unsigned* __restrict__ Bhi, const unsigned* __restrict__ Blo,
              const float* __restrict__ bias, const float* __restrict__ res,
              float* __restrict__ C, unsigned* __restrict__ Chi, unsigned* __restrict__ Clo,
              int M, int N, int K2, int act)
{
    __shared__ unsigned sAhi[2][128*12];
    __shared__ unsigned sAlo[2][128*12];
    __shared__ unsigned sBhi[2][64*12];
    __shared__ unsigned sBlo[2][64*12];

    int bm = blockIdx.y * 128, bn = blockIdx.x * 64;
    int tid = threadIdx.x;
    int warp = tid >> 5, lane = tid & 31;
    int wm = warp & 3, wn = warp >> 2;
    int g = lane >> 2, tig = lane & 3;

    // staging roles: A row am, 4 pairs at akp; B row bnr, 2 pairs at bkp
    int am = tid >> 1, akp = (tid & 1) * 4;
    int bnr = tid >> 2, bkp = (tid & 3) * 2;
    int gmA = bm + am; if (gmA >= M) gmA = 0;
    const unsigned* Aph = Ahi + (size_t)gmA * K2 + akp;
    const unsigned* Apl = Alo + (size_t)gmA * K2 + akp;
    const unsigned* Bph = Bhi + (size_t)(bn + bnr) * K2 + bkp;
    const unsigned* Bpl = Blo + (size_t)(bn + bnr) * K2 + bkp;

    uint4 rah = *(const uint4*)(Aph);
    uint4 ral = *(const uint4*)(Apl);
    uint2 rbh = *(const uint2*)(Bph);
    uint2 rbl = *(const uint2*)(Bpl);

    float acc[2][4][4];
    #pragma unroll
    for (int i = 0; i < 2; i++)
        #pragma unroll
        for (int j = 0; j < 4; j++)
            #pragma unroll
            for (int k = 0; k < 4; k++) acc[i][j][k] = 0.f;

    // prime buffer 0
    {
        unsigned* dh = &sAhi[0][am*12 + akp];
        unsigned* dl = &sAlo[0][am*12 + akp];
        dh[0]=rah.x; dh[1]=rah.y; dh[2]=rah.z; dh[3]=rah.w;
        dl[0]=ral.x; dl[1]=ral.y; dl[2]=ral.z; dl[3]=ral.w;
        unsigned* eh = &sBhi[0][bnr*12 + bkp];
        unsigned* el = &sBlo[0][bnr*12 + bkp];
        eh[0]=rbh.x; eh[1]=rbh.y;
        el[0]=rbl.x; el[1]=rbl.y;
    }
    __syncthreads();

    int nt = K2 >> 3;
    for (int t = 0; t < nt; t++) {
        int buf = t & 1;
        bool more = (t + 1 < nt);
        if (more) {
            rah = *(const uint4*)(Aph + (t+1)*8);
            ral = *(const uint4*)(Apl + (t+1)*8);
            rbh = *(const uint2*)(Bph + (t+1)*8);
            rbl = *(const uint2*)(Bpl + (t+1)*8);
        }

        unsigned aHi[2][4], aLo[2][4], bHi[4][2], bLo[4][2];
        #pragma unroll
        for (int mt = 0; mt < 2; mt++) {
            int r = wm*32 + mt*16 + g;
            aHi[mt][0] = sAhi[buf][ r     *12 + tig    ];
            aHi[mt][1] = sAhi[buf][(r + 8)*12 + tig    ];
            aHi[mt][2] = sAhi[buf][ r     *12 + tig + 4];
            aHi[mt][3] = sAhi[buf][(r + 8)*12 + tig + 4];
            aLo[mt][0] = sAlo[buf][ r     *12 + tig    ];
            aLo[mt][1] = sAlo[buf][(r + 8)*12 + tig    ];
            aLo[mt][2] = sAlo[buf][ r     *12 + tig + 4];
            aLo[mt][3] = sAlo[buf][(r + 8)*12 + tig + 4];
        }
        #pragma unroll
        for (int n2 = 0; n2 < 4; n2++) {
            int cn = wn*32 + n2*8 + g;
            bHi[n2][0] = sBhi[buf][cn*12 + tig    ];
            bHi[n2][1] = sBhi[buf][cn*12 + tig + 4];
            bLo[n2][0] = sBlo[buf][cn*12 + tig    ];
            bLo[n2][1] = sBlo[buf][cn*12 + tig + 4];
        }

        #pragma unroll
        for (int mt = 0; mt < 2; mt++)
            #pragma unroll
            for (int n2 = 0; n2 < 4; n2++) {
                MMA_BF16(acc[mt][n2], aHi[mt], bHi[n2]);
                MMA_BF16(acc[mt][n2], aHi[mt], bLo[n2]);
                MMA_BF16(acc[mt][n2], aLo[mt], bHi[n2]);
            }

        if (more) {
            int nb = buf ^ 1;
            unsigned* dh = &sAhi[nb][am*12 + akp];
            unsigned* dl = &sAlo[nb][am*12 + akp];
            dh[0]=rah.x; dh[1]=rah.y; dh[2]=rah.z; dh[3]=rah.w;
            dl[0]=ral.x; dl[1]=ral.y; dl[2]=ral.z; dl[3]=ral.w;
            unsigned* eh = &sBhi[nb][bnr*12 + bkp];
            unsigned* el = &sBlo[nb][bnr*12 + bkp];
            eh[0]=rbh.x; eh[1]=rbh.y;
            el[0]=rbl.x; el[1]=rbl.y;
        }
        __syncthreads();
    }

    int N2 = N >> 1;
    #pragma unroll
    for (int mt = 0; mt < 2; mt++) {
        #pragma unroll
        for (int n2 = 0; n2 < 4; n2++) {
            int col = bn + wn*32 + n2*8 + tig*2;
            float2 bia = *(const float2*)(bias + col);
            int r0 = bm + wm*32 + mt*16 + g;
            int r1 = r0 + 8;
            float v0 = acc[mt][n2][0] + bia.x;
            float v1 = acc[mt][n2][1] + bia.y;
            float v2 = acc[mt][n2][2] + bia.x;
            float v3 = acc[mt][n2][3] + bia.y;
            if (act == 2) {
                v0 = fmaxf(v0, 0.f); v1 = fmaxf(v1, 0.f);
                v2 = fmaxf(v2, 0.f); v3 = fmaxf(v3, 0.f);
                int cp = col >> 1;
                if (r0 < M) {
                    unsigned h, l; cvt_pair(v0, v1, h, l);
                    Chi[(size_t)r0*N2 + cp] = h; Clo[(size_t)r0*N2 + cp] = l;
                }
                if (r1 < M) {
                    unsigned h, l; cvt_pair(v2, v3, h, l);
                    Chi[(size_t)r1*N2 + cp] = h; Clo[(size_t)r1*N2 + cp] = l;
                }
            } else {
                if (r0 < M) {
                    if (res) {
                        float2 rr = *(const float2*)(res + (size_t)r0*N + col);
                        v0 += rr.x; v1 += rr.y;
                    }
                    *(float2*)(C + (size_t)r0*N + col) = make_float2(v0, v1);
                }
                if (r1 < M) {
                    if (res) {
                        float2 rr = *(const float2*)(res + (size_t)r1*N + col);
                        v2 += rr.x; v3 += rr.y;
                    }
                    *(float2*)(C + (size_t)r1*N + col) = make_float2(v2, v3);
                }
            }
        }
    }
}

// ---------------- SIMT GEMM (small-N path) ----------------
__global__ __launch_bounds__(256, 2)
void gemm_nt(const float* __restrict__ A, const float* __restrict__ Bw,
             const float* __restrict__ bias, const float* __restrict__ res,
             float* __restrict__ C, int M, int N, int K, int act, float scale)
{
    __shared__ float As[2][16][136];
    __shared__ float Bs[2][16][72];
    int bm = blockIdx.y * 128, bn = blockIdx.x * 64;
    int tid = threadIdx.x;
    int tx = tid & 15, ty = tid >> 4;

    int am = tid >> 1, ak = (tid & 1) * 8;
    int bnr = tid >> 2, bk = (tid & 3) * 4;
    int gmA = bm + am;  bool va = (gmA < M);
    int gnB = bn + bnr; bool vb = (gnB < N);
    const float* Ap = A  + (size_t)(va ? gmA : 0) * K + ak;
    const float* Bp = Bw + (size_t)(vb ? gnB : 0) * K + bk;

    const float4 fz = make_float4(0.f, 0.f, 0.f, 0.f);
    float4 a0 = va ? *(const float4*)(Ap)     : fz;
    float4 a1 = va ? *(const float4*)(Ap + 4) : fz;
    float4 b0 = vb ? *(const float4*)(Bp)     : fz;

    float acc[8][4];
    #pragma unroll
    for (int i = 0; i < 8; i++)
        #pragma unroll
        for (int j = 0; j < 4; j++) acc[i][j] = 0.f;

    As[0][ak+0][am] = a0.x; As[0][ak+1][am] = a0.y; As[0][ak+2][am] = a0.z; As[0][ak+3][am] = a0.w;
    As[0][ak+4][am] = a1.x; As[0][ak+5][am] = a1.y; As[0][ak+6][am] = a1.z; As[0][ak+7][am] = a1.w;
    Bs[0][bk+0][bnr] = b0.x; Bs[0][bk+1][bnr] = b0.y; Bs[0][bk+2][bnr] = b0.z; Bs[0][bk+3][bnr] = b0.w;
    __syncthreads();

    int nt = K >> 4;
    for (int t = 0; t < nt; t++) {
        int buf = t & 1;
        bool more = (t + 1 < nt);
        if (more) {
            const float* Ap2 = Ap + (t + 1) * 16;
            const float* Bp2 = Bp + (t + 1) * 16;
            a0 = va ? *(const float4*)(Ap2)     : fz;
            a1 = va ? *(const float4*)(Ap2 + 4) : fz;
            b0 = vb ? *(const float4*)(Bp2)     : fz;
        }
        #pragma unroll
        for (int kk = 0; kk < 16; kk++) {
            float4 x0 = *(const float4*)&As[buf][kk][ty*8];
            float4 x1 = *(const float4*)&As[buf][kk][ty*8 + 4];
            float4 y0 = *(const float4*)&Bs[buf][kk][tx*4];
            float av[8] = {x0.x,x0.y,x0.z,x0.w,x1.x,x1.y,x1.z,x1.w};
            float bv[4] = {y0.x,y0.y,y0.z,y0.w};
            #pragma unroll
            for (int i = 0; i < 8; i++)
                #pragma unroll
                for (int j = 0; j < 4; j++)
                    acc[i][j] += av[i] * bv[j];
        }
        if (more) {
            int nb = buf ^ 1;
            As[nb][ak+0][am] = a0.x; As[nb][ak+1][am] = a0.y; As[nb][ak+2][am] = a0.z; As[nb][ak+3][am] = a0.w;
            As[nb][ak+4][am] = a1.x; As[nb][ak+5][am] = a1.y; As[nb][ak+6][am] = a1.z; As[nb][ak+7][am] = a1.w;
            Bs[nb][bk+0][bnr] = b0.x; Bs[nb][bk+1][bnr] = b0.y; Bs[nb][bk+2][bnr] = b0.z; Bs[nb][bk+3][bnr] = b0.w;
        }
        __syncthreads();
    }

    #pragma unroll
    for (int i = 0; i < 8; i++) {
        int gm = bm + ty*8 + i;
        if (gm >= M) continue;
        #pragma unroll
        for (int j = 0; j < 4; j++) {
            int gn = bn + tx*4 + j;
            if (gn >= N) continue;
            float v = acc[i][j] + bias[gn];
            if (act == 1) v = fmaxf(v, 0.f);
            else if (act == 2) v = tanhf(v) * scale;
            if (res) v += res[(size_t)gm * N + gn];
            C[(size_t)gm * N + gn] = v;
        }
    }
}

// ---------------- Flash-style multi-head self-attention (split bf16 out) ----------------
#define ATT_SMEM_BYTES (23360*4)

__global__ __launch_bounds__(256, 2)
void attn_kernel(const float* __restrict__ qkv,
                 unsigned* __restrict__ ohi, unsigned* __restrict__ olo)
{
    extern __shared__ float sm[];
    float* Qs  = sm;            // [d][q] : 32 x 68
    float* Ks  = sm + 2176;     // [d][k] : 32 x 132
    float* Ps  = sm + 6400;     // [k][q] swizzled, stride 100
    float* Lsm = sm + 19200;    // [64]
    float* Vs  = sm + 19264;    // [k][d] swizzled

    int b = blockIdx.z, h = blockIdx.y;
    int q0 = blockIdx.x * 64;
    int tid = threadIdx.x;
    int tx = tid & 31, ty = tid >> 5;
    const float SCALE = 0.17677669529663687f;
    const float4 fz = make_float4(0,0,0,0);

    {
        int q = tid >> 2, dg = tid & 3;
        int gq = q0 + q;
        const float* src = qkv + (size_t)(b*NQ + (gq < NQ ? gq : 0))*768 + h*32 + dg*8;
        float4 x0 = fz, x1 = fz;
        if (gq < NQ) { x0 = *(const float4*)src; x1 = *(const float4*)(src + 4); }
        int d = dg * 8;
        Qs[(d+0)*68 + q] = x0.x; Qs[(d+1)*68 + q] = x0.y;
        Qs[(d+2)*68 + q] = x0.z; Qs[(d+3)*68 + q] = x0.w;
        Qs[(d+4)*68 + q] = x1.x; Qs[(d+5)*68 + q] = x1.y;
        Qs[(d+6)*68 + q] = x1.z; Qs[(d+7)*68 + q] = x1.w;
    }

    float o[8][4];
    float m[8], l[8];
    #pragma unroll
    for (int i = 0; i < 8; i++) {
        m[i] = -1e30f; l[i] = 0.f;
        #pragma unroll
        for (int j = 0; j < 4; j++) o[i][j] = 0.f;
    }

    int kg = tx >> 3, dgi = tx & 7;

    for (int c = 0; c < 8; c++) {
        int kc0 = c * 128;

        {
            int k = tid >> 1, dg = tid & 1;
            int kglob = kc0 + k;
            const float* src = qkv + (size_t)(b*NQ + (kglob < NQ ? kglob : 0))*768 + 256 + h*32 + dg*16;
            float4 x0 = fz, x1 = fz, x2 = fz, x3 = fz;
            if (kglob < NQ) {
                x0 = *(const float4*)(src);      x1 = *(const float4*)(src + 4);
                x2 = *(const float4*)(src + 8);  x3 = *(const float4*)(src + 12);
            }
            int d = dg * 16;
            Ks[(d+ 0)*132 + k] = x0.x; Ks[(d+ 1)*132 + k] = x0.y;
            Ks[(d+ 2)*132 + k] = x0.z; Ks[(d+ 3)*132 + k] = x0.w;
            Ks[(d+ 4)*132 + k] = x1.x; Ks[(d+ 5)*132 + k] = x1.y;
            Ks[(d+ 6)*132 + k] = x1.z; Ks[(d+ 7)*132 + k] = x1.w;
            Ks[(d+ 8)*132 + k] = x2.x; Ks[(d+ 9)*132 + k] = x2.y;
            Ks[(d+10)*132 + k] = x2.z; Ks[(d+11)*132 + k] = x2.w;
            Ks[(d+12)*132 + k] = x3.x; Ks[(d+13)*132 + k] = x3.y;
            Ks[(d+14)*132 + k] = x3.z; Ks[(d+15)*132 + k] = x3.w;
        }
        {
            int k = tid >> 1, dv = (tid & 1) * 16;
            int kglob = kc0 + k;
            const float* src = qkv + (size_t)(b*NQ + (kglob < NQ ? kglob : 0))*768 + 512 + h*32 + dv;
            float4 v0 = fz, v1 = fz, v2 = fz, v3 = fz;
            if (kglob < NQ) {
                v0 = *(const float4*)(src);      v1 = *(const float4*)(src + 4);
                v2 = *(const float4*)(src + 8);  v3 = *(const float4*)(src + 12);
            }
            int dq = dv >> 2;
            *(float4*)(Vs + k*32 + (((dq + 0) + k) & 7)*4) = v0;
            *(float4*)(Vs + k*32 + (((dq + 1) + k) & 7)*4) = v1;
            *(float4*)(Vs + k*32 + (((dq + 2) + k) & 7)*4) = v2;
            *(float4*)(Vs + k*32 + (((dq + 3) + k) & 7)*4) = v3;
        }
        __syncthreads();

        float acc[8][4];
        #pragma unroll
        for (int i = 0; i < 8; i++)
            #pragma unroll
            for (int j = 0; j < 4; j++) acc[i][j] = 0.f;

        #pragma unroll 8
        for (int d = 0; d < 32; d++) {
            const float4* Q4 = (const float4*)(Qs + d*68);
            float4 qa = Q4[ty*2], qb = Q4[ty*2 + 1];
            float4 kv = ((const float4*)(Ks + d*132))[tx];
            float qq[8] = {qa.x,qa.y,qa.z,qa.w,qb.x,qb.y,qb.z,qb.w};
            #pragma unroll
            for (int i = 0; i < 8; i++) {
                acc[i][0] += qq[i] * kv.x;
                acc[i][1] += qq[i] * kv.y;
                acc[i][2] += qq[i] * kv.z;
                acc[i][3] += qq[i] * kv.w;
            }
        }

        #pragma unroll
        for (int j = 0; j < 4; j++) {
            bool vk = (kc0 + tx*4 + j) < NQ;
            #pragma unroll
            for (int i = 0; i < 8; i++)
                acc[i][j] = vk ? acc[i][j]*SCALE : -1e30f;
        }

        #pragma unroll
        for (int i = 0; i < 8; i++) {
            float rm = fmaxf(fmaxf(acc[i][0], acc[i][1]), fmaxf(acc[i][2], acc[i][3]));
            #pragma unroll
            for (int off = 16; off; off >>= 1) rm = fmaxf(rm, __shfl_xor_sync(0xffffffffu, rm, off));
            float mn = fmaxf(m[i], rm);
            float alpha = __expf(m[i] - mn);
            m[i] = mn;
            float ls = 0.f;
            #pragma unroll
            for (int j = 0; j < 4; j++) {
                float p = __expf(acc[i][j] - mn);
                acc[i][j] = p;
                ls += p;
            }
            #pragma unroll
            for (int off = 16; off; off >>= 1) ls += __shfl_xor_sync(0xffffffffu, ls, off);
            l[i] = l[i]*alpha + ls;
            #pragma unroll
            for (int j = 0; j < 4; j++) o[i][j] *= alpha;
        }

        {
            int sw = (tx & 7) * 4;
            #pragma unroll
            for (int j = 0; j < 4; j++) {
                float* dst = Ps + (tx*4 + j)*100 + sw + ty*8;
                *(float4*)(dst)     = make_float4(acc[0][j], acc[1][j], acc[2][j], acc[3][j]);
                *(float4*)(dst + 4) = make_float4(acc[4][j], acc[5][j], acc[6][j], acc[7][j]);
            }
        }
        __syncthreads();

        {
            #pragma unroll 8
            for (int i2 = 0; i2 < 32; i2++) {
                int k = 4*i2 + kg;
                const float* prow = Ps + k*100 + (i2 & 7)*4;
                float4 pa = *(const float4*)(prow + ty*8);
                float4 pb = *(const float4*)(prow + ty*8 + 4);
                float4 v = *(const float4*)(Vs + k*32 + ((dgi + k) & 7)*4);
                float pv[8] = {pa.x,pa.y,pa.z,pa.w,pb.x,pb.y,pb.z,pb.w};
                #pragma unroll
                for (int i = 0; i < 8; i++) {
                    o[i][0] += pv[i] * v.x;
                    o[i][1] += pv[i] * v.y;
                    o[i][2] += pv[i] * v.z;
                    o[i][3] += pv[i] * v.w;
                }
            }
        }
        __syncthreads();
    }

    float* red = Ps;
    #pragma unroll
    for (int i = 0; i < 8; i++) {
        float* dst = red + kg*2048 + (ty*8 + i)*32 + dgi*4;
        *(float4*)dst = make_float4(o[i][0], o[i][1], o[i][2], o[i][3]);
    }
    if (tx == 0) {
        #pragma unroll
        for (int i = 0; i < 8; i++) Lsm[ty*8 + i] = l[i];
    }
    __syncthreads();

    {
        int q = tid >> 2, dgrp = tid & 3;
        int gq = q0 + q;
        if (gq < NQ) {
            int d = dgrp * 8;
            float s0 = 0, s1 = 0, s2 = 0, s3 = 0, s4 = 0, s5 = 0, s6 = 0, s7 = 0;
            #pragma unroll
            for (int g2 = 0; g2 < 4; g2++) {
                const float* src = red + g2*2048 + q*32 + d;
                float4 u = *(const float4*)(src);
                float4 w = *(const float4*)(src + 4);
                s0 += u.x; s1 += u.y; s2 += u.z; s3 += u.w;
                s4 += w.x; s5 += w.y; s6 += w.z; s7 += w.w;
            }
            float linv = 1.f / Lsm[q];
            // split bf16 hi/lo out: pairs along d
            unsigned h0,l0,h1,l1,h2,l2,h3,l3;
            cvt_pair(s0*linv, s1*linv, h0, l0);
            cvt_pair(s2*linv, s3*linv, h1, l1);
            cvt_pair(s4*linv, s5*linv, h2, l2);
            cvt_pair(s6*linv, s7*linv, h3, l3);
            size_t basep = (size_t)(b*NQ + gq)*128 + h*16 + dgrp*4;
            *(uint4*)(ohi + basep) = make_uint4(h0, h1, h2, h3);
            *(uint4*)(olo + basep) = make_uint4(l0, l1, l2, l3);
        }
    }
}

// ---------------- BEV bilinear sampling + softmax + fuse (split bf16 out) ----------------
__global__ void sample_kernel(const float* __restrict__ mem, const float* __restrict__ ref,
                              const float* __restrict__ off, const float* __restrict__ wt,
                              unsigned* __restrict__ ohi, unsigned* __restrict__ olo)
{
    int idx = blockIdx.x * 256 + threadIdx.x;
    if (idx >= M_ROWS * DD) return;
    int c = idx & 31;
    int h = (idx >> 5) & 7;
    int row = idx >> 8;
    int b = row / NQ;

    float rx = ref[row*2 + 0], ry = ref[row*2 + 1];
    const float* offr = off + (size_t)row*64 + h*8;
    const float* wtr  = wt  + (size_t)row*32 + h*4;
    const float* memb = mem + (size_t)b * (BEV*BEV) * DD + h*HD + c;

    float w0 = wtr[0], w1 = wtr[1], w2 = wtr[2], w3 = wtr[3];
    float wm = fmaxf(fmaxf(w0, w1), fmaxf(w2, w3));
    float e0 = __expf(w0 - wm), e1 = __expf(w1 - wm), e2 = __expf(w2 - wm), e3 = __expf(w3 - wm);
    float winv = 1.f / (e0 + e1 + e2 + e3);
    float wsm[4] = {e0*winv, e1*winv, e2*winv, e3*winv};

    float acc = 0.f;
    #pragma unroll
    for (int p = 0; p < PP; p++) {
        float gx = (rx + offr[p*2 + 0]) * (float)BEV - 0.5f;
        float gy = (ry + offr[p*2 + 1]) * (float)BEV - 0.5f;
        float x0f = floorf(gx), y0f = floorf(gy);
        int x0 = (int)x0f, y0 = (int)y0f;
        float wx1 = gx - x0f, wy1 = gy - y0f;
        float wx0 = 1.f - wx1, wy0 = 1.f - wy1;
        float v = 0.f;
        if ((unsigned)x0     < BEV && (unsigned)y0     < BEV) v += wx0*wy0 * memb[(size_t)(y0*BEV + x0    )*DD];
        if ((unsigned)(x0+1) < BEV && (unsigned)y0     < BEV) v += wx1*wy0 * memb[(size_t)(y0*BEV + x0 + 1)*DD];
        if ((unsigned)x0     < BEV && (unsigned)(y0+1) < BEV) v += wx0*wy1 * memb[(size_t)((y0+1)*BEV + x0    )*DD];
        if ((unsigned)(x0+1) < BEV && (unsigned)(y0+1) < BEV) v += wx1*wy1 * memb[(size_t)((y0+1)*BEV + x0 + 1)*DD];
        acc += wsm[p] * v;
    }
    // pair with neighbor thread (idx and idx+1 same warp), even writes split u32
    float acc2 = __shfl_down_sync(0xffffffffu, acc, 1);
    if (!(idx & 1)) {
        unsigned hh, ll;
        cvt_pair(acc, acc2, hh, ll);
        ohi[idx >> 1] = hh;
        olo[idx >> 1] = ll;
    }
}

// ---------------- launch ----------------
extern "C" void kernel_launch(void* const* d_in, const int* in_sizes, int n_in,
                              void* d_out, int out_size)
{
    const float* query   = (const float*)d_in[0];
    const float* memory  = (const float*)d_in[1];
    const float* refpts  = (const float*)d_in[2];
    const float* qpos    = (const float*)d_in[3];
    const float* in_w    = (const float*)d_in[4];
    const float* in_b    = (const float*)d_in[5];
    const float* out_w   = (const float*)d_in[6];
    const float* out_b   = (const float*)d_in[7];
    const float* off_w   = (const float*)d_in[8];
    const float* off_b   = (const float*)d_in[9];
    const float* wt_w    = (const float*)d_in[10];
    const float* wt_b    = (const float*)d_in[11];
    const float* co_w    = (const float*)d_in[12];
    const float* co_b    = (const float*)d_in[13];
    const float* f_w1    = (const float*)d_in[14];
    const float* f_b1    = (const float*)d_in[15];
    const float* f_w2    = (const float*)d_in[16];
    const float* f_b2    = (const float*)d_in[17];
    const float* n1s     = (const float*)d_in[18];
    const float* n1b     = (const float*)d_in[19];
    const float* n2s     = (const float*)d_in[20];
    const float* n2b     = (const float*)d_in[21];
    const float* n3s     = (const float*)d_in[22];
    const float* n3b     = (const float*)d_in[23];

    float* base = nullptr;
    cudaGetSymbolAddress((void**)&base, g_scratch);
    unsigned* ub = (unsigned*)base;

    float* qkv  = base + OFF_QKV;
    float* q1   = base + OFF_Q1;
    float* q2   = base + OFF_Q2;
    float* qu2  = base + OFF_QU2;
    float* off  = base + OFF_OFFS;
    float* wt   = base + OFF_WT;
    unsigned *qinH = ub + OFF_QINH, *qinL = ub + OFF_QINL;
    unsigned *attH = ub + OFF_ATTH, *attL = ub + OFF_ATTL;
    unsigned *fusH = ub + OFF_FUSH, *fusL = ub + OFF_FUSL;
    unsigned *q3H  = ub + OFF_Q3H,  *q3L  = ub + OFF_Q3L;
    unsigned *h1H  = ub + OFF_H1H,  *h1L  = ub + OFF_H1L;
    unsigned *wiH  = ub + OFF_WIH,  *wiL  = ub + OFF_WIL;
    unsigned *woH  = ub + OFF_WOH,  *woL  = ub + OFF_WOL;
    unsigned *wcH  = ub + OFF_WCH,  *wcL  = ub + OFF_WCL;
    unsigned *w1H  = ub + OFF_W1H,  *w1L  = ub + OFF_W1L;
    unsigned *w2H  = ub + OFF_W2H,  *w2L  = ub + OFF_W2L;

    cudaFuncSetAttribute(attn_kernel, cudaFuncAttributeMaxDynamicSharedMemorySize, ATT_SMEM_BYTES);

    const int GY = (M_ROWS + 127) / 128;   // 57

    // 0) split weights (graph-captured each run; cheap)
    split_kernel<<<(768*128 + 255)/256, 256>>>(in_w,  wiH, wiL, 768*128);
    split_kernel<<<(256*128 + 255)/256, 256>>>(out_w, woH, woL, 256*128);
    split_kernel<<<(256*128 + 255)/256, 256>>>(co_w,  wcH, wcL, 256*128);
    split_kernel<<<(512*128 + 255)/256, 256>>>(f_w1,  w1H, w1L, 512*128);
    split_kernel<<<(256*256 + 255)/256, 256>>>(f_w2,  w2H, w2L, 256*256);

    // 1) q_in = LN(query + pos; n1) -> split
    ln_split_kernel<<<M_ROWS, 256>>>(query, qpos, n1s, n1b, qinH, qinL);
    // 2) qkv = q_in @ in_w^T + in_b
    gemm_tc2<<<dim3(12, GY), 256>>>(qinH, qinL, wiH, wiL, in_b, nullptr, qkv, nullptr, nullptr,
                                    M_ROWS, 768, 128, 0);
    // 3) self-attention (flash) -> split attn
    attn_kernel<<<dim3((NQ + 63) / 64, HH, BB), 256, ATT_SMEM_BYTES>>>(qkv, attH, attL);
    // 4) query1 = query + attn @ out_w^T + out_b
    gemm_tc2<<<dim3(4, GY), 256>>>(attH, attL, woH, woL, out_b, query, q1, nullptr, nullptr,
                                   M_ROWS, 256, 128, 0);
    // 5) q2 = LN(query1 + pos; n2) (f32, feeds SIMT gemms)
    ln_kernel<<<M_ROWS, 256>>>(q1, qpos, n2s, n2b, q2);
    // 6) offsets = tanh(q2 @ off_w^T + off_b) * RADIUS
    gemm_nt<<<dim3(1, GY), 256>>>(q2, off_w, off_b, nullptr, off, M_ROWS, 64, 256, 2, 0.2f);
    // 7) raw weights
    gemm_nt<<<dim3(1, GY), 256>>>(q2, wt_w, wt_b, nullptr, wt, M_ROWS, 32, 256, 0, 0.f);
    // 8) bilinear sample + softmax + fuse -> split fus
    sample_kernel<<<(M_ROWS * DD + 255) / 256, 256>>>(memory, refpts, off, wt, fusH, fusL);
    // 9) query2 = query1 + fused @ co_w^T + co_b
    gemm_tc2<<<dim3(4, GY), 256>>>(fusH, fusL, wcH, wcL, co_b, q1, qu2, nullptr, nullptr,
                                   M_ROWS, 256, 128, 0);
    // 10) q3 = LN(query2; n3) -> split
    ln_split_kernel<<<M_ROWS, 256>>>(qu2, nullptr, n3s, n3b, q3H, q3L);
    // 11) h1 = relu(q3 @ f_w1^T + f_b1) -> split h1 directly
    gemm_tc2<<<dim3(8, GY), 256>>>(q3H, q3L, w1H, w1L, f_b1, nullptr, nullptr, h1H, h1L,
                                   M_ROWS, 512, 128, 2);
    // 12) out = query2 + h1 @ f_w2^T + f_b2   (K=512 -> K2=256)
    gemm_tc2<<<dim3(4, GY), 256>>>(h1H, h1L, w2H, w2L, f_b2, qu2, (float*)d_out, nullptr, nullptr,
                                   M_ROWS, 256, 256, 0);
}